// round 17
// baseline (speedup 1.0000x reference)
#include <cuda_runtime.h>
#include <cuda_bf16.h>
#include <cstdint>
#include <math.h>

#define TOKENS 16384
#define D_IN   2048
#define D_HID  1024
#define N_EXP  64
#define TOPK   8
#define SLOPE  0.01f
#define KSPLIT1 512   // GEMM1: 4 panels of 512, sequential folds (FROZEN)
#define KSPLIT2 256   // GEMM2: 4 panels of 256, pairwise-tree fold (FROZEN)

// Scratch for hidden activations H [TOKENS, D_HID] (64 MB)
__device__ float g_H[(size_t)TOKENS * D_HID];

// ---- packed f32x2 helpers (each half rounds exactly like scalar fmaf/add) --
__device__ __forceinline__ void fma2(uint64_t& d, uint64_t a, uint64_t b) {
    asm("fma.rn.f32x2 %0, %1, %2, %0;" : "+l"(d) : "l"(a), "l"(b));
}
__device__ __forceinline__ void unpack2(float& lo, float& hi, uint64_t v) {
    asm("mov.b64 {%0, %1}, %2;" : "=f"(lo), "=f"(hi) : "l"(v));
}

// ---------------------------------------------------------------------------
// GEMM1: H = leaky_relu(X @ W1^T + b1)
// NUMERICS (frozen): 4 panels of 512; per-element ascending FMA chain within
// panel; sequential panel folds; packed f32x2 along n-pairs.
// Schedule: tot in smem (2 blocks/SM) + DUPLICATED-A smem layout:
// As[k][2m]=As[k][2m+1]=X[m][k], so one LDS.128 delivers two packed (a,a)
// operands — eliminates all 8 mov.b64 broadcasts per k.
// Smem/block: As 16KB + Bs 8KB + totS 64KB = 88KB (2 blocks = 176 <= 227KB).
// ---------------------------------------------------------------------------
#define BM 128
#define BN 128
#define BK 16
#define TM 8
#define TN 8

#define SM_AS    0                          // BK * 2*BM floats (duplicated)
#define SM_BS    (BK * 2 * BM)              // BK * BN floats
#define SM_TOT   (BK * 2 * BM + BK * BN)    // 64 * 256 floats
#define SM1_FLOATS (BK * 2 * BM + BK * BN + 64 * 256)   // 22528 floats = 88KB

__global__ __launch_bounds__(256, 2)
void gemm1_kernel(const float* __restrict__ X,
                  const float* __restrict__ W1,
                  const float* __restrict__ b1)
{
    extern __shared__ float smemPool[];
    float* As   = smemPool + SM_AS;    // [k][2m] duplicated pairs
    float* Bs   = smemPool + SM_BS;    // [k][n]
    float* totS = smemPool + SM_TOT;   // [elem][tid]

    const int block_m = blockIdx.y * BM;
    const int block_n = blockIdx.x * BN;
    const int tid  = threadIdx.x;
    const int trow = tid / 16;
    const int tcol = tid % 16;

    #pragma unroll
    for (int e = 0; e < 64; e++) totS[e * 256 + tid] = 0.f;

    uint64_t accP[TM][TN / 2];
    const uint64_t z2 = 0ull;
    #pragma unroll
    for (int i = 0; i < TM; i++)
        #pragma unroll
        for (int jp = 0; jp < TN / 2; jp++) accP[i][jp] = z2;

    for (int k0 = 0; k0 < D_IN; k0 += BK) {
        #pragma unroll
        for (int j = 0; j < 2; j++) {
            int idx = tid + j * 256;
            int row = idx >> 2;
            int k4  = (idx & 3) * 4;
            float4 v = *(const float4*)(X  + (size_t)(block_m + row) * D_IN + k0 + k4);
            // duplicated stores: (v,v) as float2 each
            *(float2*)&As[(k4 + 0) * (2 * BM) + 2 * row] = make_float2(v.x, v.x);
            *(float2*)&As[(k4 + 1) * (2 * BM) + 2 * row] = make_float2(v.y, v.y);
            *(float2*)&As[(k4 + 2) * (2 * BM) + 2 * row] = make_float2(v.z, v.z);
            *(float2*)&As[(k4 + 3) * (2 * BM) + 2 * row] = make_float2(v.w, v.w);
            float4 w = *(const float4*)(W1 + (size_t)(block_n + row) * D_IN + k0 + k4);
            Bs[(k4 + 0) * BN + row] = w.x; Bs[(k4 + 1) * BN + row] = w.y;
            Bs[(k4 + 2) * BN + row] = w.z; Bs[(k4 + 3) * BN + row] = w.w;
        }
        __syncthreads();

        #pragma unroll
        for (int k = 0; k < BK; k++) {
            // a packed pairs: 4 LDS.128, each = (a_i,a_i,a_{i+1},a_{i+1})
            uint64_t aP[TM];
            #pragma unroll
            for (int q = 0; q < 4; q++) {
                float4 av = *(const float4*)&As[k * (2 * BM) + trow * (2 * TM) + q * 4];
                aP[q * 2 + 0] = *(const uint64_t*)&av.x;
                aP[q * 2 + 1] = *(const uint64_t*)&av.z;
            }
            float4 b0 = *(const float4*)&Bs[k * BN + tcol * TN];
            float4 b1v= *(const float4*)&Bs[k * BN + tcol * TN + 4];
            uint64_t bP[4];
            bP[0] = *(const uint64_t*)&b0.x;
            bP[1] = *(const uint64_t*)&b0.z;
            bP[2] = *(const uint64_t*)&b1v.x;
            bP[3] = *(const uint64_t*)&b1v.z;

            #pragma unroll
            for (int i = 0; i < TM; i++)
                #pragma unroll
                for (int jp = 0; jp < TN / 2; jp++)
                    fma2(accP[i][jp], aP[i], bP[jp]);
        }
        __syncthreads();

        if (((k0 + BK) % KSPLIT1) == 0) {   // sequential panel fold (frozen)
            #pragma unroll
            for (int i = 0; i < TM; i++)
                #pragma unroll
                for (int jp = 0; jp < TN / 2; jp++) {
                    float lo, hi;
                    unpack2(lo, hi, accP[i][jp]);
                    int e = i * TN + jp * 2;
                    totS[e * 256 + tid]       += lo;
                    totS[(e + 1) * 256 + tid] += hi;
                    accP[i][jp] = z2;
                }
        }
    }

    #pragma unroll
    for (int i = 0; i < TM; i++) {
        int m = block_m + trow * TM + i;
        #pragma unroll
        for (int j4 = 0; j4 < TN; j4 += 4) {
            int n = block_n + tcol * TN + j4;
            int e = i * TN + j4;
            float v0 = totS[(e + 0) * 256 + tid] + b1[n+0];
            float v1 = totS[(e + 1) * 256 + tid] + b1[n+1];
            float v2 = totS[(e + 2) * 256 + tid] + b1[n+2];
            float v3 = totS[(e + 3) * 256 + tid] + b1[n+3];
            float4 o;
            o.x = v0 >= 0.f ? v0 : SLOPE * v0;
            o.y = v1 >= 0.f ? v1 : SLOPE * v1;
            o.z = v2 >= 0.f ? v2 : SLOPE * v2;
            o.w = v3 >= 0.f ? v3 : SLOPE * v3;
            *(float4*)(g_H + (size_t)m * D_HID + n) = o;
        }
    }
}

// ---------------------------------------------------------------------------
// GEMM2: logits = H @ W2^T + b2.  (R11-passing version, verbatim)
// 4 panels of 256 ascending chains, pairwise tree (p0+p1)+(p2+p3).
// Fused top-8 + softmax. 64 tokens x 64 experts per block, 256 threads.
// ---------------------------------------------------------------------------
#define K2CHUNK 32

__global__ __launch_bounds__(256)
void gemm2_topk_kernel(const float* __restrict__ W2,
                       const float* __restrict__ b2,
                       float* __restrict__ out,
                       int out_size)
{
    __shared__ float Hs[K2CHUNK][64];
    __shared__ float Ws[K2CHUNK][64];
    __shared__ float ls[64][N_EXP + 1];

    const int tok0 = blockIdx.x * 64;
    const int tid  = threadIdx.x;
    const int ttok = (tid / 16) * 4;
    const int texp = (tid % 16) * 4;

    float acc[4][4];
    float pan[4][4][4];
    #pragma unroll
    for (int i = 0; i < 4; i++)
        #pragma unroll
        for (int j = 0; j < 4; j++) {
            acc[i][j] = 0.f;
            #pragma unroll
            for (int p = 0; p < 4; p++) pan[p][i][j] = 0.f;
        }

    int panel = 0;
    for (int k0 = 0; k0 < D_HID; k0 += K2CHUNK) {
        #pragma unroll
        for (int j = 0; j < 2; j++) {
            int idx = tid + j * 256;
            int row = idx >> 3;
            int k4  = (idx & 7) * 4;
            float4 h = *(const float4*)(g_H + (size_t)(tok0 + row) * D_HID + k0 + k4);
            Hs[k4 + 0][row] = h.x; Hs[k4 + 1][row] = h.y;
            Hs[k4 + 2][row] = h.z; Hs[k4 + 3][row] = h.w;
            float4 w = *(const float4*)(W2 + (size_t)row * D_HID + k0 + k4);
            Ws[k4 + 0][row] = w.x; Ws[k4 + 1][row] = w.y;
            Ws[k4 + 2][row] = w.z; Ws[k4 + 3][row] = w.w;
        }
        __syncthreads();

        #pragma unroll
        for (int k = 0; k < K2CHUNK; k++) {
            float4 a = *(const float4*)&Hs[k][ttok];
            float4 b = *(const float4*)&Ws[k][texp];
            float av[4] = {a.x, a.y, a.z, a.w};
            float bv[4] = {b.x, b.y, b.z, b.w};
            #pragma unroll
            for (int i = 0; i < 4; i++)
                #pragma unroll
                for (int j = 0; j < 4; j++)
                    acc[i][j] = fmaf(av[i], bv[j], acc[i][j]);
        }
        __syncthreads();

        if (((k0 + K2CHUNK) % KSPLIT2) == 0) {   // stash panel (frozen)
            #pragma unroll
            for (int i = 0; i < 4; i++)
                #pragma unroll
                for (int j = 0; j < 4; j++) {
                    pan[panel][i][j] = acc[i][j];
                    acc[i][j] = 0.f;
                }
            panel++;
        }
    }

    // Pairwise-tree combine + bias (frozen)
    #pragma unroll
    for (int i = 0; i < 4; i++)
        #pragma unroll
        for (int j = 0; j < 4; j++) {
            float lo = pan[0][i][j] + pan[1][i][j];
            float hi = pan[2][i][j] + pan[3][i][j];
            ls[ttok + i][texp + j] = (lo + hi) + b2[texp + j];
        }
    __syncthreads();

    // Top-8 + softmax (frozen semantics)
    if (tid < 64) {
        const int t = tid;
        float vals[TOPK];
        int   idxs[TOPK];
        uint64_t taken = 0ull;
        #pragma unroll
        for (int j = 0; j < TOPK; j++) {
            float best = -3.4e38f;
            int bi = 0;
            for (int e = 0; e < N_EXP; e++) {
                bool free_ = !((taken >> e) & 1ull);
                float v = ls[t][e];
                if (free_ && v > best) { best = v; bi = e; }
            }
            taken |= (1ull << bi);
            vals[j] = best;
            idxs[j] = bi;
        }
        double m = (double)vals[0];
        double e8[TOPK];
        double s = 0.0;
        #pragma unroll
        for (int j = 0; j < TOPK; j++) { e8[j] = exp((double)vals[j] - m); s += e8[j]; }
        const int gt = tok0 + t;
        #pragma unroll
        for (int j = 0; j < TOPK; j++)
            out[(size_t)gt * TOPK + j] = (float)(e8[j] / s);
        if (out_size >= 2 * TOKENS * TOPK) {
            float* oid = out + (size_t)TOKENS * TOPK;
            #pragma unroll
            for (int j = 0; j < TOPK; j++)
                oid[(size_t)gt * TOPK + j] = (float)idxs[j];
        }
    }
}

// ---------------------------------------------------------------------------
extern "C" void kernel_launch(void* const* d_in, const int* in_sizes, int n_in,
                              void* d_out, int out_size)
{
    const float* X  = (const float*)d_in[0];
    const float* W1 = (const float*)d_in[1];
    const float* b1 = (const float*)d_in[2];
    const float* W2 = (const float*)d_in[3];
    const float* b2 = (const float*)d_in[4];
    float* out = (float*)d_out;

    static int attr_set = 0;
    if (!attr_set) {
        cudaFuncSetAttribute(gemm1_kernel,
                             cudaFuncAttributeMaxDynamicSharedMemorySize,
                             SM1_FLOATS * (int)sizeof(float));
        attr_set = 1;
    }

    dim3 g1(D_HID / BN, TOKENS / BM);   // (8, 128)
    gemm1_kernel<<<g1, 256, SM1_FLOATS * sizeof(float)>>>(X, W1, b1);

    gemm2_topk_kernel<<<TOKENS / 64, 256>>>(W2, b2, out, out_size);
}